// round 6
// baseline (speedup 1.0000x reference)
#include <cuda_runtime.h>
#include <cstdint>
#include <cstddef>

#define N_NODES   25
#define K_TOT     384
#define OUT_F     256
#define M_TOT     (8192 * 25)
#define NEG_BIG   (-9e15f)
#define MAXNB     24
#define NCH       12

// ---- shared memory layout (all tiles 128B-row swizzled) ----
#define OFF_X   0          // [2][128 rows][32 f]          32 KB
#define OFF_A0  32768      // [2][128][16 f2] swizzled     32 KB
#define OFF_AZ  65536      //                              32 KB
#define OFF_B   98304      // [2][512 n][16 f2] swizzled  128 KB
#define OFF_MT  229376
#define MT_DIAG 0          // 25 f
#define MT_NNZ  128        // 25 i
#define MT_PK   256        // 600 u32 (coef bits | src)
#define DSMEM   232064

__device__ float    g_WTp[2 * OUT_F * K_TOT];   // [half][n][paired pos], rna
__device__ float    g_diag[N_NODES];
__device__ int      g_nnzc[N_NODES];
__device__ uint32_t g_pk[N_NODES * MAXNB];      // (coef & ~31) | src

// ---------------- helpers ----------------
__device__ __forceinline__ float rna_tf32(float x) {
    uint32_t u; asm("cvt.rna.tf32.f32 %0, %1;" : "=r"(u) : "f"(x));
    return __uint_as_float(u);
}
__device__ __forceinline__ void cpa16(void* dst, const float* src) {
    uint32_t d = (uint32_t)__cvta_generic_to_shared(dst);
    asm volatile("cp.async.cg.shared.global [%0], [%1], 16;" :: "r"(d), "l"(src));
}
__device__ __forceinline__ void mma8(float c[4], float2 alo, float2 ahi, float2 b) {
    asm volatile(
        "mma.sync.aligned.m16n8k8.row.col.f32.tf32.tf32.f32 "
        "{%0,%1,%2,%3}, {%4,%5,%6,%7}, {%8,%9}, {%0,%1,%2,%3};\n"
        : "+f"(c[0]), "+f"(c[1]), "+f"(c[2]), "+f"(c[3])
        : "r"(__float_as_uint(alo.x)), "r"(__float_as_uint(ahi.x)),
          "r"(__float_as_uint(alo.y)), "r"(__float_as_uint(ahi.y)),
          "r"(__float_as_uint(b.x)),  "r"(__float_as_uint(b.y)));
}
#define COMMIT() asm volatile("cp.async.commit_group;")
#define WAITG1() asm volatile("cp.async.wait_group 1;")

// ================= setup ==================================================
__global__ void setup_kernel(const float* __restrict__ W,
                             const float* __restrict__ e,
                             const int*   __restrict__ rows,
                             const int*   __restrict__ cols,
                             int nnz) {
    const int total = 2 * OUT_F * K_TOT;
    for (int i = blockIdx.x * blockDim.x + threadIdx.x; i < total;
         i += gridDim.x * blockDim.x) {
        int h   = i / (OUT_F * K_TOT);
        int rem = i - h * (OUT_F * K_TOT);
        int n   = rem / K_TOT;
        int pos = rem - n * K_TOT;
        int ch = pos >> 5, r5 = pos & 31;
        int g = r5 >> 3, q = r5 & 7;
        int lc = q >> 1, h4 = q & 1;
        int k = ch * 32 + g * 8 + h4 * 4 + lc;
        g_WTp[i] = rna_tf32(W[h * (K_TOT * OUT_F) + k * OUT_F + n]);
    }
    if (blockIdx.x == 0) {
        __shared__ float lg[N_NODES * N_NODES];
        int t = threadIdx.x;
        for (int i = t; i < N_NODES * N_NODES; i += blockDim.x) lg[i] = NEG_BIG;
        __syncthreads();
        for (int i = t; i < nnz; i += blockDim.x) lg[rows[i] * N_NODES + cols[i]] = e[i];
        __syncthreads();
        if (t < N_NODES) {
            float mx = -1e30f;
            #pragma unroll
            for (int n = 0; n < N_NODES; n++) mx = fmaxf(mx, lg[t * N_NODES + n]);
            float ex[N_NODES]; float s = 0.f;
            #pragma unroll
            for (int n = 0; n < N_NODES; n++) {
                ex[n] = expf(lg[t * N_NODES + n] - mx); s += ex[n];
            }
            float inv = 1.f / s;
            int cnt = 0;
            for (int n = 0; n < N_NODES; n++) {
                float a = ex[n] * inv;
                if (n == t) g_diag[t] = a;
                else if (lg[t * N_NODES + n] != NEG_BIG) {
                    g_pk[t * MAXNB + cnt] =
                        (__float_as_uint(a) & 0xFFFFFFE0u) | (uint32_t)n;
                    cnt++;
                }
            }
            g_nnzc[t] = cnt;
        }
    }
}

// ================= fused premix + tf32 GEMM (512 threads) =================
__global__ void __launch_bounds__(512, 1)
fused_kernel(const float* __restrict__ nodev, const float* __restrict__ hid,
             const float* __restrict__ bias, float* __restrict__ out) {
    extern __shared__ char sm[];
    const int tid = threadIdx.x, wid = tid >> 5, lid = tid & 31;
    const int lr = lid >> 2, lc = lid & 3;
    const int wm = wid >> 2, wn = wid & 3;       // 4 x 4 warp grid
    const int row0  = blockIdx.x * 125;
    const int nrows = (M_TOT - row0 < 125) ? (M_TOT - row0) : 125;
    const int nbat  = nrows / 25;

    float*    s_diag = (float*)(sm + OFF_MT + MT_DIAG);
    int*      s_nnz  = (int*)  (sm + OFF_MT + MT_NNZ);
    uint32_t* s_pk   = (uint32_t*)(sm + OFF_MT + MT_PK);

    if (tid < N_NODES) { s_diag[tid] = g_diag[tid]; s_nnz[tid] = g_nnzc[tid]; }
    for (int i = tid; i < N_NODES * MAXNB; i += 512) s_pk[i] = g_pk[i];

    // ---- loaders (512 threads) ----
    auto fillX = [&](int s, int xb) {
        const int k0 = s * 32;
        #pragma unroll
        for (int i = 0; i < 2; i++) {
            int idx = i * 512 + tid;
            int row = idx >> 3, g = idx & 7;
            int grow = row0 + row; if (grow >= M_TOT) grow = M_TOT - 1;
            const float* src = (k0 < 128)
                ? (nodev + (size_t)grow * 128 + k0 + g * 4)
                : (hid   + (size_t)grow * 256 + (k0 - 128) + g * 4);
            cpa16(sm + OFF_X + xb * 16384 + row * 128 + g * 16, src);
        }
    };
    auto fillB = [&](int s, int bb) {
        #pragma unroll
        for (int i = 0; i < 8; i++) {
            int idx = i * 512 + tid;
            int n = idx >> 3, g = idx & 7;
            int h = n >> 8, nn = n & 255;
            cpa16(sm + OFF_B + bb * 65536 + n * 128 + ((g ^ (n & 7)) << 4),
                  g_WTp + (size_t)h * (OUT_F * K_TOT) + (size_t)nn * K_TOT
                        + s * 32 + g * 4);
        }
    };

    __syncthreads();    // meta visible before premix use

    // ---- premix constants: this warp owns rows wid*8 .. wid*8+7 ----
    const int pm_ks = lid >> 3, pm_r3 = lid & 7;
    const int pm_p  = pm_ks * 4 + (pm_r3 & 3);
    const int pm_h4 = pm_r3 >> 2;
    float pdiag[8]; int ppack[8]; int pxb[8]; uint32_t poff[8];
    #pragma unroll
    for (int r = 0; r < 8; r++) {
        int m = wid * 8 + r;
        int bl = (m * 1311) >> 15;
        if (bl > nbat - 1) bl = nbat - 1;
        int node = m - bl * 25; if (node > 24) node = 24;
        pdiag[r] = s_diag[node];
        ppack[r] = node * MAXNB * 32 + s_nnz[node];   // (base<<5)|nn
        pxb[r]   = bl * 25 * 32 + lid;
        poff[r]  = (uint32_t)(m * 128)
                 + ((uint32_t)((pm_p >> 1) ^ (m & 7)) << 4)
                 + (pm_p & 1) * 8 + pm_h4 * 4;
    }

    auto premix = [&](int sIdx) {
        const int buf = sIdx & 1;
        const float* X = (const float*)(sm + OFF_X + buf * 16384);
        char* A0 = sm + OFF_A0 + buf * 16384;
        char* AZ = sm + OFF_AZ + buf * 16384;
        #pragma unroll
        for (int r = 0; r < 8; r++) {
            int m = wid * 8 + r;
            float x = X[m * 32 + lid];
            float a0 = pdiag[r] * x;
            float z = 0.f;
            int nn = ppack[r] & 31;
            const uint32_t* pk = s_pk + (ppack[r] >> 5);
            const float* Xb = X + pxb[r];
            #pragma unroll 4
            for (int j = 0; j < nn; j++) {
                uint32_t u = pk[j];
                z += __uint_as_float(u & 0xFFFFFFE0u) * Xb[(u & 31u) * 32];
            }
            *(float*)(A0 + poff[r]) = rna_tf32(a0);
            *(float*)(AZ + poff[r]) = rna_tf32(z);
        }
    };

    // ---- prologue ----
    fillX(0, 0); fillB(0, 0); COMMIT();
    fillX(1, 1); fillB(1, 1); COMMIT();
    WAITG1(); __syncthreads();          // {X0,B0} visible
    premix(0);
    __syncthreads();                    // A(0) ready
    fillX(2, 0); COMMIT();

    float acc[2][8][4];
    #pragma unroll
    for (int a = 0; a < 2; a++)
        #pragma unroll
        for (int b = 0; b < 8; b++)
            #pragma unroll
            for (int c = 0; c < 4; c++) acc[a][b][c] = 0.f;

    const int c1 = lc >> 1, c2 = (lc & 1) * 8;

    // ---- main loop ----
    #pragma unroll 1
    for (int s = 0; s < NCH; s++) {
        const int buf = s & 1;
        WAITG1();
        __syncthreads();

        const char* Bbase = sm + OFF_B + buf * 65536;

        // pass 0: A0 @ W0
        {
            const char* Ab = sm + OFF_A0 + buf * 16384;
            #pragma unroll
            for (int ks = 0; ks < 4; ks++) {
                float2 alo[2], ahi[2];
                #pragma unroll
                for (int mf = 0; mf < 2; mf++) {
                    int r0 = wm * 32 + mf * 16 + lr;
                    uint32_t go = (uint32_t)(((2 * ks + c1) ^ lr) << 4) + c2;
                    alo[mf] = *(const float2*)(Ab + r0 * 128 + go);
                    ahi[mf] = *(const float2*)(Ab + (r0 + 8) * 128 + go);
                }
                #pragma unroll
                for (int nf = 0; nf < 8; nf++) {
                    int n = wn * 64 + nf * 8 + lr;
                    float2 b = *(const float2*)(Bbase + n * 128 +
                               (uint32_t)(((2 * ks + c1) ^ (n & 7)) << 4) + c2);
                    #pragma unroll
                    for (int mf = 0; mf < 2; mf++) mma8(acc[mf][nf], alo[mf], ahi[mf], b);
                }
            }
        }

        if (s + 1 < NCH) premix(s + 1);

        // pass 1: AZ @ W1
        {
            const char* Ab = sm + OFF_AZ + buf * 16384;
            #pragma unroll
            for (int ks = 0; ks < 4; ks++) {
                float2 alo[2], ahi[2];
                #pragma unroll
                for (int mf = 0; mf < 2; mf++) {
                    int r0 = wm * 32 + mf * 16 + lr;
                    uint32_t go = (uint32_t)(((2 * ks + c1) ^ lr) << 4) + c2;
                    alo[mf] = *(const float2*)(Ab + r0 * 128 + go);
                    ahi[mf] = *(const float2*)(Ab + (r0 + 8) * 128 + go);
                }
                #pragma unroll
                for (int nf = 0; nf < 8; nf++) {
                    int n = 256 + wn * 64 + nf * 8 + lr;
                    float2 b = *(const float2*)(Bbase + n * 128 +
                               (uint32_t)(((2 * ks + c1) ^ (n & 7)) << 4) + c2);
                    #pragma unroll
                    for (int mf = 0; mf < 2; mf++) mma8(acc[mf][nf], alo[mf], ahi[mf], b);
                }
            }
        }

        __syncthreads();
        if (s + 3 < NCH) fillX(s + 3, (s + 3) & 1);
        if (s + 2 < NCH) fillB(s + 2, buf);
        COMMIT();
    }

    // ---- epilogue: acc + bias -> out ----
    #pragma unroll
    for (int mf = 0; mf < 2; mf++) {
        const int m0 = wm * 32 + mf * 16 + lr;
        const bool v0 = m0 < nrows, v1 = (m0 + 8) < nrows;
        float* o0 = out + ((size_t)row0 + m0) * OUT_F;
        float* o1 = out + ((size_t)row0 + m0 + 8) * OUT_F;
        #pragma unroll
        for (int nf = 0; nf < 8; nf++) {
            const int c = wn * 64 + nf * 8 + lc * 2;
            float2 bv = __ldg((const float2*)(bias + c));
            if (v0) *(float2*)(o0 + c) =
                make_float2(acc[mf][nf][0] + bv.x, acc[mf][nf][1] + bv.y);
            if (v1) *(float2*)(o1 + c) =
                make_float2(acc[mf][nf][2] + bv.x, acc[mf][nf][3] + bv.y);
        }
    }
}

// ================= launcher ==============================================
extern "C" void kernel_launch(void* const* d_in, const int* in_sizes, int n_in,
                              void* d_out, int out_size) {
    const float* nodev = (const float*)d_in[0];
    const float* hid   = (const float*)d_in[1];
    const float* W     = (const float*)d_in[2];
    const float* e     = (const float*)d_in[3];
    const float* bias  = (const float*)d_in[4];
    const int*   rows  = (const int*)d_in[5];
    const int*   cols  = (const int*)d_in[6];
    const int nnz = in_sizes[3];

    setup_kernel<<<64, 256>>>(W, e, rows, cols, nnz);

    cudaFuncSetAttribute(fused_kernel,
                         cudaFuncAttributeMaxDynamicSharedMemorySize, DSMEM);
    const int grid = (M_TOT + 124) / 125;   // 1639
    fused_kernel<<<grid, 512, DSMEM>>>(nodev, hid, bias, (float*)d_out);
    (void)n_in; (void)out_size;
}

// round 7
// speedup vs baseline: 1.4436x; 1.4436x over previous
#include <cuda_runtime.h>
#include <cstdint>
#include <cstddef>

#define N_NODES 25
#define K_TOT   384
#define OUT_F   256
#define M_TOT   (8192 * 25)
#define NEG_BIG (-9e15f)
#define MAXNB   24
#define NCH     12

// ---- smem layout ----
#define TILE_STRIDE 49152          // per stage: A 16KB + B 32KB
#define OFF_A(i)  ((i) * TILE_STRIDE)
#define OFF_B(i)  ((i) * TILE_STRIDE + 16384)
#define OFF_HS    0                // reused after mainloop: [64 cols][284 f]
#define HS_STRIDE 284
#define OFF_G     196608           // 32 x 58 f
#define G_STRIDE  58
#define OFF_BIAS  204032           // 128 f
#define DSMEM     204800

__device__ float    g_WTp[2 * OUT_F * K_TOT];   // [half][n][paired pos], rna
__device__ float    g_diag[N_NODES];
__device__ int      g_nnzc[N_NODES];
__device__ uint32_t g_pk[N_NODES * MAXNB];      // (coef bits & ~31) | src

// ---------------- helpers ----------------
__device__ __forceinline__ uint32_t tf32b(float x) {
    uint32_t u; asm("cvt.rna.tf32.f32 %0, %1;" : "=r"(u) : "f"(x));
    return u;
}
__device__ __forceinline__ float tf32f(float x) {
    return __uint_as_float(tf32b(x));
}
__device__ __forceinline__ void cpa16(void* dst, const float* src) {
    uint32_t d = (uint32_t)__cvta_generic_to_shared(dst);
    asm volatile("cp.async.cg.shared.global [%0], [%1], 16;" :: "r"(d), "l"(src));
}
__device__ __forceinline__ void mma8u(float c[4], uint32_t a0, uint32_t a1,
                                      uint32_t a2, uint32_t a3,
                                      uint32_t b0, uint32_t b1) {
    asm volatile(
        "mma.sync.aligned.m16n8k8.row.col.f32.tf32.tf32.f32 "
        "{%0,%1,%2,%3}, {%4,%5,%6,%7}, {%8,%9}, {%0,%1,%2,%3};\n"
        : "+f"(c[0]), "+f"(c[1]), "+f"(c[2]), "+f"(c[3])
        : "r"(a0), "r"(a1), "r"(a2), "r"(a3), "r"(b0), "r"(b1));
}
#define COMMIT() asm volatile("cp.async.commit_group;")
#define WAITG2() asm volatile("cp.async.wait_group 2;")

// ================= setup ==================================================
__global__ void setup_kernel(const float* __restrict__ W,
                             const float* __restrict__ e,
                             const int*   __restrict__ rows,
                             const int*   __restrict__ cols,
                             int nnz) {
    // pos pairing: pos = ch*32 + g*8 + lc*2 + h4  <->  k = ch*32 + g*8 + h4*4 + lc
    const int total = 2 * OUT_F * K_TOT;
    for (int i = blockIdx.x * blockDim.x + threadIdx.x; i < total;
         i += gridDim.x * blockDim.x) {
        int h   = i / (OUT_F * K_TOT);
        int rem = i - h * (OUT_F * K_TOT);
        int n   = rem / K_TOT;
        int pos = rem - n * K_TOT;
        int ch = pos >> 5, r5 = pos & 31;
        int g = r5 >> 3, q = r5 & 7;
        int lc = q >> 1, h4 = q & 1;
        int k = ch * 32 + g * 8 + h4 * 4 + lc;
        g_WTp[i] = __uint_as_float(tf32b(W[h * (K_TOT * OUT_F) + k * OUT_F + n]));
    }
    if (blockIdx.x == 0) {
        __shared__ float lg[N_NODES * N_NODES];
        int t = threadIdx.x;
        for (int i = t; i < N_NODES * N_NODES; i += blockDim.x) lg[i] = NEG_BIG;
        __syncthreads();
        for (int i = t; i < nnz; i += blockDim.x) lg[rows[i] * N_NODES + cols[i]] = e[i];
        __syncthreads();
        if (t < N_NODES) {
            float mx = -1e30f;
            #pragma unroll
            for (int n = 0; n < N_NODES; n++) mx = fmaxf(mx, lg[t * N_NODES + n]);
            float ex[N_NODES]; float s = 0.f;
            #pragma unroll
            for (int n = 0; n < N_NODES; n++) {
                ex[n] = expf(lg[t * N_NODES + n] - mx); s += ex[n];
            }
            float inv = 1.f / s;
            int cnt = 0;
            for (int n = 0; n < N_NODES; n++) {
                float a = ex[n] * inv;
                if (n == t) g_diag[t] = a;
                else if (lg[t * N_NODES + n] != NEG_BIG) {
                    g_pk[t * MAXNB + cnt] =
                        (__float_as_uint(a) & 0xFFFFFFE0u) | (uint32_t)n;
                    cnt++;
                }
            }
            g_nnzc[t] = cnt;
        }
    }
}

// ================= fused GEMM + output-mix MMA ============================
__global__ void __launch_bounds__(512, 1)
fused_kernel(const float* __restrict__ nodev, const float* __restrict__ hid,
             const float* __restrict__ bias, float* __restrict__ out) {
    extern __shared__ char sm[];
    const int tid = threadIdx.x, wid = tid >> 5, lid = tid & 31;
    const int lr = lid >> 2, lc = lid & 3;
    const int wm = wid >> 2, wn = wid & 3;       // 4m x 4n warp grid
    const int c1 = lc >> 1, c2 = (lc & 1) * 8;

    const int rb = blockIdx.x >> 1, cb = blockIdx.x & 1;
    const int row0 = rb * 125;
    const int j0   = cb * 128;
    const int nrows = (M_TOT - row0 < 125) ? (M_TOT - row0) : 125;

    // ---- tile loaders ----
    auto fillX = [&](int s, int b) {
        const int k0 = s * 32;
        #pragma unroll
        for (int i = 0; i < 2; i++) {
            int idx = i * 512 + tid;
            int row = idx >> 3, g = idx & 7;
            int grow = row0 + row; if (grow >= M_TOT) grow = M_TOT - 1;
            const float* src = (k0 < 128)
                ? (nodev + (size_t)grow * 128 + k0 + g * 4)
                : (hid   + (size_t)grow * 256 + (k0 - 128) + g * 4);
            cpa16(sm + OFF_A(b) + row * 128 + ((g ^ (row & 7)) << 4), src);
        }
    };
    auto fillB = [&](int s, int b) {
        #pragma unroll
        for (int i = 0; i < 4; i++) {
            int idx = i * 512 + tid;
            int n = idx >> 3, g = idx & 7;
            int h = n >> 7, ncol = j0 + (n & 127);
            cpa16(sm + OFF_B(b) + n * 128 + ((g ^ (n & 7)) << 4),
                  g_WTp + (size_t)h * (OUT_F * K_TOT) + (size_t)ncol * K_TOT
                        + s * 32 + g * 4);
        }
    };

    // ---- prologue: get DRAM going, then build G/bias ----
    fillX(0, 0); fillB(0, 0); COMMIT();
    fillX(1, 1); fillB(1, 1); COMMIT();
    fillX(2, 2); fillB(2, 2); COMMIT();

    float* G = (float*)(sm + OFF_G);
    for (int i = tid; i < 32 * G_STRIDE; i += 512) G[i] = 0.f;
    if (tid < 128) ((float*)(sm + OFF_BIAS))[tid] = bias[j0 + tid];
    __syncthreads();
    if (tid < N_NODES) {
        G[tid * G_STRIDE + tid] = tf32f(g_diag[tid]);
        int nn = g_nnzc[tid];
        for (int j = 0; j < nn; j++) {
            uint32_t u = g_pk[tid * MAXNB + j];
            G[tid * G_STRIDE + 25 + (u & 31u)] =
                tf32f(__uint_as_float(u & 0xFFFFFFE0u));
        }
    }

    float acc[2][8][4];
    #pragma unroll
    for (int a = 0; a < 2; a++)
        #pragma unroll
        for (int b = 0; b < 8; b++)
            #pragma unroll
            for (int c = 0; c < 4; c++) acc[a][b][c] = 0.f;

    // ---- main loop: one barrier per chunk, 4-stage pipeline ----
    #pragma unroll 1
    for (int s = 0; s < NCH; s++) {
        const int buf = s & 3;
        WAITG2();
        __syncthreads();
        if (s + 3 < NCH) { fillX(s + 3, (s + 3) & 3); fillB(s + 3, (s + 3) & 3); }
        COMMIT();

        const char* Ab = sm + OFF_A(buf);
        const char* Bb = sm + OFF_B(buf);
        #pragma unroll
        for (int ks = 0; ks < 4; ks++) {
            uint32_t a[2][4];
            #pragma unroll
            for (int mf = 0; mf < 2; mf++) {
                int r0 = wm * 32 + mf * 16 + lr;
                int r1 = r0 + 8;
                a[mf][0] = tf32b(*(const float*)(Ab + r0 * 128 + (((2 * ks)     ^ (r0 & 7)) << 4) + lc * 4));
                a[mf][1] = tf32b(*(const float*)(Ab + r1 * 128 + (((2 * ks)     ^ (r1 & 7)) << 4) + lc * 4));
                a[mf][2] = tf32b(*(const float*)(Ab + r0 * 128 + (((2 * ks + 1) ^ (r0 & 7)) << 4) + lc * 4));
                a[mf][3] = tf32b(*(const float*)(Ab + r1 * 128 + (((2 * ks + 1) ^ (r1 & 7)) << 4) + lc * 4));
            }
            #pragma unroll
            for (int nf = 0; nf < 8; nf++) {
                int n = wn * 64 + nf * 8 + lr;
                float2 b = *(const float2*)(Bb + n * 128 +
                           (uint32_t)(((2 * ks + c1) ^ (n & 7)) << 4) + c2);
                #pragma unroll
                for (int mf = 0; mf < 2; mf++)
                    mma8u(acc[mf][nf], a[mf][0], a[mf][1], a[mf][2], a[mf][3],
                          __float_as_uint(b.x), __float_as_uint(b.y));
            }
        }
    }

    // ================= epilogue: out = G @ Hcat + bias ====================
    __syncthreads();    // tile smem dead -> becomes Hs

    // zero the k-padding rows (krow 50..55 per batch) once
    for (int i = tid; i < 64 * 30; i += 512) {
        int col = i / 30, r = i % 30;
        int b = r / 6, kp = 50 + r % 6;
        *(float*)(sm + OFF_HS + (size_t)col * (HS_STRIDE * 4) + (b * 56 + kp) * 4) = 0.f;
    }

    const int isH1 = wn >> 1;
    #pragma unroll 1
    for (int p = 0; p < 2; p++) {
        __syncthreads();
        // stage acc -> Hs[col_local][krow]  (cols p*64 .. p*64+63)
        if ((wn & 1) == p) {
            #pragma unroll
            for (int mf = 0; mf < 2; mf++) {
                #pragma unroll
                for (int h = 0; h < 2; h++) {
                    int R = wm * 32 + mf * 16 + lr + h * 8;
                    if (R < 125) {
                        int b = (R * 1311) >> 15;      // R/25
                        int node = R - b * 25;
                        int krow = b * 56 + node + isH1 * 25;
                        #pragma unroll
                        for (int nf = 0; nf < 8; nf++) {
                            int cl = nf * 8 + lc * 2;
                            *(float*)(sm + OFF_HS + (size_t)cl * (HS_STRIDE * 4) + krow * 4)
                                = tf32f(acc[mf][nf][h * 2]);
                            *(float*)(sm + OFF_HS + (size_t)(cl + 1) * (HS_STRIDE * 4) + krow * 4)
                                = tf32f(acc[mf][nf][h * 2 + 1]);
                        }
                    }
                }
            }
        }
        __syncthreads();

        // mix MMAs: 40 tasks = 5 batches x 8 n-frags
        #pragma unroll 1
        for (int t = wid; t < 40; t += 16) {
            int b = t >> 3, nf = t & 7;
            float macc[2][4];
            #pragma unroll
            for (int mf = 0; mf < 2; mf++)
                #pragma unroll
                for (int e = 0; e < 4; e++) macc[mf][e] = 0.f;

            #pragma unroll
            for (int kf = 0; kf < 7; kf++) {
                const char* hsb = sm + OFF_HS
                    + (size_t)(nf * 8 + lr) * (HS_STRIDE * 4)
                    + (b * 56 + kf * 8 + lc) * 4;
                uint32_t bx = __float_as_uint(*(const float*)(hsb));
                uint32_t by = __float_as_uint(*(const float*)(hsb + 16));
                #pragma unroll
                for (int mf = 0; mf < 2; mf++) {
                    int r = mf * 16 + lr;
                    const float* g0 = G + r * G_STRIDE + kf * 8 + lc;
                    uint32_t a0 = __float_as_uint(g0[0]);
                    uint32_t a2 = __float_as_uint(g0[4]);
                    uint32_t a1 = 0, a3 = 0;
                    if (r + 8 < 32) {
                        const float* g1 = G + (r + 8) * G_STRIDE + kf * 8 + lc;
                        a1 = __float_as_uint(g1[0]);
                        a3 = __float_as_uint(g1[4]);
                    }
                    mma8u(macc[mf], a0, a1, a2, a3, bx, by);
                }
            }
            // write out + bias
            #pragma unroll
            for (int mf = 0; mf < 2; mf++) {
                #pragma unroll
                for (int h = 0; h < 2; h++) {
                    int m = mf * 16 + lr + h * 8;
                    int lrow = b * 25 + m;
                    if (m < 25 && lrow < nrows) {
                        int cl = p * 64 + nf * 8 + lc * 2;
                        float2 bv = *(const float2*)(sm + OFF_BIAS + cl * 4);
                        *(float2*)(out + ((size_t)row0 + lrow) * OUT_F + j0 + cl) =
                            make_float2(macc[mf][h * 2] + bv.x,
                                        macc[mf][h * 2 + 1] + bv.y);
                    }
                }
            }
        }
    }
}

// ================= launcher ==============================================
extern "C" void kernel_launch(void* const* d_in, const int* in_sizes, int n_in,
                              void* d_out, int out_size) {
    const float* nodev = (const float*)d_in[0];
    const float* hid   = (const float*)d_in[1];
    const float* W     = (const float*)d_in[2];
    const float* e     = (const float*)d_in[3];
    const float* bias  = (const float*)d_in[4];
    const int*   rows  = (const int*)d_in[5];
    const int*   cols  = (const int*)d_in[6];
    const int nnz = in_sizes[3];

    setup_kernel<<<64, 256>>>(W, e, rows, cols, nnz);

    cudaFuncSetAttribute(fused_kernel,
                         cudaFuncAttributeMaxDynamicSharedMemorySize, DSMEM);
    const int grid = ((M_TOT + 124) / 125) * 2;   // 3278
    fused_kernel<<<grid, 512, DSMEM>>>(nodev, hid, bias, (float*)d_out);
    (void)n_in; (void)out_size;
}

// round 8
// speedup vs baseline: 1.8401x; 1.2747x over previous
#include <cuda_runtime.h>
#include <cstdint>
#include <cstddef>

#define N_NODES 25
#define K_TOT   384
#define OUT_F   256
#define M_TOT   (8192 * 25)
#define NEG_BIG (-9e15f)
#define MAXNB   24
#define NCH     12

// ---- smem layout ----
#define STG_SZ   49152                  // per stage: A 16KB + B 32KB
#define OFF_A(i) ((i) * STG_SZ)
#define OFF_B(i) ((i) * STG_SZ + 16384)
#define OFF_HS   0                      // epilogue reuse: [128 cols][284 f]
#define HS_STRIDE 284
#define OFF_G    147456                 // 32 x 57 f
#define G_STRIDE 57
#define OFF_BIAS 154752                 // 128 f
#define DSMEM    155264

__device__ float    g_WTp[2 * OUT_F * K_TOT];   // [h][n][k-quad pos], rna
__device__ float    g_diag[N_NODES];
__device__ int      g_nnzc[N_NODES];
__device__ uint32_t g_pk[N_NODES * MAXNB];

// ---------------- helpers ----------------
__device__ __forceinline__ uint32_t tf32b(float x) {
    uint32_t u; asm("cvt.rna.tf32.f32 %0, %1;" : "=r"(u) : "f"(x));
    return u;
}
__device__ __forceinline__ float tf32f(float x) { return __uint_as_float(tf32b(x)); }
__device__ __forceinline__ void cpa16(void* dst, const float* src) {
    uint32_t d = (uint32_t)__cvta_generic_to_shared(dst);
    asm volatile("cp.async.cg.shared.global [%0], [%1], 16;" :: "r"(d), "l"(src));
}
__device__ __forceinline__ void mma8u(float c[4], uint32_t a0, uint32_t a1,
                                      uint32_t a2, uint32_t a3,
                                      uint32_t b0, uint32_t b1) {
    asm volatile(
        "mma.sync.aligned.m16n8k8.row.col.f32.tf32.tf32.f32 "
        "{%0,%1,%2,%3}, {%4,%5,%6,%7}, {%8,%9}, {%0,%1,%2,%3};\n"
        : "+f"(c[0]), "+f"(c[1]), "+f"(c[2]), "+f"(c[3])
        : "r"(a0), "r"(a1), "r"(a2), "r"(a3), "r"(b0), "r"(b1));
}
#define COMMIT() asm volatile("cp.async.commit_group;")
#define WAITG1() asm volatile("cp.async.wait_group 1;")

// ================= setup ==================================================
__global__ void setup_kernel(const float* __restrict__ W,
                             const float* __restrict__ e,
                             const int*   __restrict__ rows,
                             const int*   __restrict__ cols,
                             int nnz) {
    // k-quad layout: pos = ch*32 + q*4 + ee,  k = ch*32 + 16*(q>>2) + (q&3) + 4*ee
    const int total = 2 * OUT_F * K_TOT;
    for (int i = blockIdx.x * blockDim.x + threadIdx.x; i < total;
         i += gridDim.x * blockDim.x) {
        int h   = i / (OUT_F * K_TOT);
        int rem = i - h * (OUT_F * K_TOT);
        int n   = rem / K_TOT;
        int pos = rem - n * K_TOT;
        int ch = pos >> 5, r5 = pos & 31;
        int q = r5 >> 2, ee = r5 & 3;
        int k = ch * 32 + ((q >> 2) << 4) + (q & 3) + (ee << 2);
        g_WTp[i] = __uint_as_float(tf32b(W[h * (K_TOT * OUT_F) + k * OUT_F + n]));
    }
    if (blockIdx.x == 0) {
        __shared__ float lg[N_NODES * N_NODES];
        int t = threadIdx.x;
        for (int i = t; i < N_NODES * N_NODES; i += blockDim.x) lg[i] = NEG_BIG;
        __syncthreads();
        for (int i = t; i < nnz; i += blockDim.x) lg[rows[i] * N_NODES + cols[i]] = e[i];
        __syncthreads();
        if (t < N_NODES) {
            float mx = -1e30f;
            #pragma unroll
            for (int n = 0; n < N_NODES; n++) mx = fmaxf(mx, lg[t * N_NODES + n]);
            float ex[N_NODES]; float s = 0.f;
            #pragma unroll
            for (int n = 0; n < N_NODES; n++) {
                ex[n] = expf(lg[t * N_NODES + n] - mx); s += ex[n];
            }
            float inv = 1.f / s;
            int cnt = 0;
            for (int n = 0; n < N_NODES; n++) {
                float a = ex[n] * inv;
                if (n == t) g_diag[t] = a;
                else if (lg[t * N_NODES + n] != NEG_BIG) {
                    g_pk[t * MAXNB + cnt] =
                        (__float_as_uint(a) & 0xFFFFFFE0u) | (uint32_t)n;
                    cnt++;
                }
            }
            g_nnzc[t] = cnt;
        }
    }
}

// ================= fused GEMM + output-mix MMA ============================
__global__ void __launch_bounds__(256, 1)
fused_kernel(const float* __restrict__ nodev, const float* __restrict__ hid,
             const float* __restrict__ bias, float* __restrict__ out) {
    extern __shared__ char sm[];
    const int tid = threadIdx.x, wid = tid >> 5, lid = tid & 31;
    const int lr = lid >> 2, lc = lid & 3;
    const int wm = wid >> 2, wn = wid & 3;       // 2m x 4n warp grid
    const int rb = blockIdx.x >> 1, cb = blockIdx.x & 1;
    const int row0 = rb * 125;
    const int j0   = cb * 128;
    const int nrows = (M_TOT - row0 < 125) ? (M_TOT - row0) : 125;

    // ---- loaders (256 threads) ----
    auto fillX = [&](int s, int b) {
        const int k0 = s * 32;
        #pragma unroll
        for (int i = 0; i < 4; i++) {
            int idx = i * 256 + tid;
            int row = idx >> 3, g = idx & 7;
            int grow = row0 + row; if (grow >= M_TOT) grow = M_TOT - 1;
            const float* src = (k0 < 128)
                ? (nodev + (size_t)grow * 128 + k0 + g * 4)
                : (hid   + (size_t)grow * 256 + (k0 - 128) + g * 4);
            cpa16(sm + OFF_A(b) + row * 128 + ((g ^ (row & 7)) << 4), src);
        }
    };
    auto fillB = [&](int s, int b) {
        #pragma unroll
        for (int i = 0; i < 8; i++) {
            int idx = i * 256 + tid;
            int n = idx >> 3, g = idx & 7;
            int h = n >> 7, ncol = j0 + (n & 127);
            cpa16(sm + OFF_B(b) + n * 128 + ((g ^ (n & 7)) << 4),
                  g_WTp + (size_t)h * (OUT_F * K_TOT) + (size_t)ncol * K_TOT
                        + s * 32 + g * 4);
        }
    };

    // ---- prologue: 2 stages in flight, then G/bias ----
    fillX(0, 0); fillB(0, 0); COMMIT();
    fillX(1, 1); fillB(1, 1); COMMIT();

    float* G = (float*)(sm + OFF_G);
    for (int i = tid; i < 32 * G_STRIDE; i += 256) G[i] = 0.f;
    if (tid < 128) ((float*)(sm + OFF_BIAS))[tid] = bias[j0 + tid];
    __syncthreads();
    if (tid < N_NODES) {
        G[tid * G_STRIDE + tid] = tf32f(g_diag[tid]);
        int nn = g_nnzc[tid];
        for (int j = 0; j < nn; j++) {
            uint32_t u = g_pk[tid * MAXNB + j];
            G[tid * G_STRIDE + 25 + (u & 31u)] =
                tf32f(__uint_as_float(u & 0xFFFFFFE0u));
        }
    }

    float acc[4][8][4];
    #pragma unroll
    for (int a = 0; a < 4; a++)
        #pragma unroll
        for (int b = 0; b < 8; b++)
            #pragma unroll
            for (int c = 0; c < 4; c++) acc[a][b][c] = 0.f;

    // ---- main loop ----
    #pragma unroll 1
    for (int s = 0; s < NCH; s++) {
        const int buf = s % 3;
        WAITG1();
        __syncthreads();
        if (s + 2 < NCH) { fillX(s + 2, (s + 2) % 3); fillB(s + 2, (s + 2) % 3); }
        COMMIT();

        const char* Ab = sm + OFF_A(buf);
        const char* Bb = sm + OFF_B(buf);

        #pragma unroll
        for (int p = 0; p < 2; p++) {
            float4 bq[8];
            #pragma unroll
            for (int nf = 0; nf < 8; nf++) {
                int n = wn * 64 + nf * 8 + lr;
                bq[nf] = *(const float4*)(Bb + n * 128 +
                          (((p * 4 + lc) ^ (n & 7)) << 4));
            }
            #pragma unroll
            for (int ks01 = 0; ks01 < 2; ks01++) {
                const int ks = 2 * p + ks01;
                uint32_t a[4][4];
                #pragma unroll
                for (int mf = 0; mf < 4; mf++) {
                    int r0 = wm * 64 + mf * 16 + lr;
                    int r1 = r0 + 8;
                    a[mf][0] = tf32b(*(const float*)(Ab + r0 * 128 + (((2 * ks)     ^ (r0 & 7)) << 4) + lc * 4));
                    a[mf][1] = tf32b(*(const float*)(Ab + r1 * 128 + (((2 * ks)     ^ (r1 & 7)) << 4) + lc * 4));
                    a[mf][2] = tf32b(*(const float*)(Ab + r0 * 128 + (((2 * ks + 1) ^ (r0 & 7)) << 4) + lc * 4));
                    a[mf][3] = tf32b(*(const float*)(Ab + r1 * 128 + (((2 * ks + 1) ^ (r1 & 7)) << 4) + lc * 4));
                }
                #pragma unroll
                for (int nf = 0; nf < 8; nf++) {
                    uint32_t b0 = __float_as_uint(ks01 ? bq[nf].z : bq[nf].x);
                    uint32_t b1 = __float_as_uint(ks01 ? bq[nf].w : bq[nf].y);
                    #pragma unroll
                    for (int mf = 0; mf < 4; mf++)
                        mma8u(acc[mf][nf], a[mf][0], a[mf][1], a[mf][2], a[mf][3],
                              b0, b1);
                }
            }
        }
    }

    // ================= epilogue: out = G @ Hcat + bias ====================
    __syncthreads();    // tile smem dead -> Hs

    // zero padding rows (krow 50..55 per batch), 128 cols
    for (int i = tid; i < 128 * 30; i += 256) {
        int col = i / 30, r = i % 30;
        int b = r / 6, kp = 50 + r % 6;
        *(float*)(sm + OFF_HS + (size_t)col * (HS_STRIDE * 4) + (b * 56 + kp) * 4) = 0.f;
    }
    __syncthreads();

    // stage acc -> Hs[col][krow]
    {
        const int isH1 = wn >> 1;
        const int cl0  = (wn & 1) * 64;
        #pragma unroll
        for (int mf = 0; mf < 4; mf++) {
            #pragma unroll
            for (int h = 0; h < 2; h++) {
                int R = wm * 64 + mf * 16 + lr + h * 8;
                if (R < 125) {
                    int b = (R * 1311) >> 15;
                    int node = R - b * 25;
                    int krow = b * 56 + node + isH1 * 25;
                    #pragma unroll
                    for (int nf = 0; nf < 8; nf++) {
                        int cl = cl0 + nf * 8 + lc * 2;
                        *(float*)(sm + OFF_HS + (size_t)cl * (HS_STRIDE * 4) + krow * 4)
                            = tf32f(acc[mf][nf][h * 2]);
                        *(float*)(sm + OFF_HS + (size_t)(cl + 1) * (HS_STRIDE * 4) + krow * 4)
                            = tf32f(acc[mf][nf][h * 2 + 1]);
                    }
                }
            }
        }
    }
    __syncthreads();

    // mix MMAs: 80 tasks = 5 batches x 16 col-frags
    #pragma unroll 1
    for (int t = wid; t < 80; t += 8) {
        int b = t >> 4, nfc = t & 15;
        float macc[2][4];
        #pragma unroll
        for (int mf = 0; mf < 2; mf++)
            #pragma unroll
            for (int e = 0; e < 4; e++) macc[mf][e] = 0.f;

        #pragma unroll
        for (int kf = 0; kf < 7; kf++) {
            const char* hsb = sm + OFF_HS
                + (size_t)(nfc * 8 + lr) * (HS_STRIDE * 4)
                + (b * 56 + kf * 8 + lc) * 4;
            uint32_t bx = __float_as_uint(*(const float*)(hsb));
            uint32_t by = __float_as_uint(*(const float*)(hsb + 16));
            #pragma unroll
            for (int mf = 0; mf < 2; mf++) {
                int r = mf * 16 + lr;
                const float* g0 = G + r * G_STRIDE + kf * 8 + lc;
                const float* g1 = G + (r + 8) * G_STRIDE + kf * 8 + lc;
                mma8u(macc[mf],
                      __float_as_uint(g0[0]), __float_as_uint(g1[0]),
                      __float_as_uint(g0[4]), __float_as_uint(g1[4]),
                      bx, by);
            }
        }
        #pragma unroll
        for (int mf = 0; mf < 2; mf++) {
            #pragma unroll
            for (int h = 0; h < 2; h++) {
                int m = mf * 16 + lr + h * 8;
                int lrow = b * 25 + m;
                if (m < 25 && lrow < nrows) {
                    int cl = nfc * 8 + lc * 2;
                    float2 bv = *(const float2*)(sm + OFF_BIAS + cl * 4);
                    *(float2*)(out + ((size_t)row0 + lrow) * OUT_F + j0 + cl) =
                        make_float2(macc[mf][h * 2] + bv.x,
                                    macc[mf][h * 2 + 1] + bv.y);
                }
            }
        }
    }
}

// ================= launcher ==============================================
extern "C" void kernel_launch(void* const* d_in, const int* in_sizes, int n_in,
                              void* d_out, int out_size) {
    const float* nodev = (const float*)d_in[0];
    const float* hid   = (const float*)d_in[1];
    const float* W     = (const float*)d_in[2];
    const float* e     = (const float*)d_in[3];
    const float* bias  = (const float*)d_in[4];
    const int*   rows  = (const int*)d_in[5];
    const int*   cols  = (const int*)d_in[6];
    const int nnz = in_sizes[3];

    setup_kernel<<<64, 256>>>(W, e, rows, cols, nnz);

    cudaFuncSetAttribute(fused_kernel,
                         cudaFuncAttributeMaxDynamicSharedMemorySize, DSMEM);
    const int grid = ((M_TOT + 124) / 125) * 2;   // 3278
    fused_kernel<<<grid, 256, DSMEM>>>(nodev, hid, bias, (float*)d_out);
    (void)n_in; (void)out_size;
}